// round 2
// baseline (speedup 1.0000x reference)
#include <cuda_runtime.h>

#define NN 1024
#define BN 4096
#define NH 8
#define TI 16
#define TJ 32

typedef unsigned long long ull;

// ---- scratch (no allocations allowed) ----
__device__ float g_V[BN*128];
__device__ float g_SKIP[BN*128];
__device__ float g_A1[BN*NH];
__device__ float g_A2[BN*NH];
__device__ float g_ATTG[4*NH];

// ---- packed f32x2 helpers ----
__device__ __forceinline__ ull ffma2(ull a, ull b, ull c) {
    ull d; asm("fma.rn.f32x2 %0,%1,%2,%3;" : "=l"(d) : "l"(a), "l"(b), "l"(c)); return d;
}
__device__ __forceinline__ ull fadd2(ull a, ull b) {
    ull d; asm("add.rn.f32x2 %0,%1,%2;" : "=l"(d) : "l"(a), "l"(b)); return d;
}
__device__ __forceinline__ ull fmul2(ull a, ull b) {
    ull d; asm("mul.rn.f32x2 %0,%1,%2;" : "=l"(d) : "l"(a), "l"(b)); return d;
}
__device__ __forceinline__ ull pack2(float x, float y) {
    ull r; asm("mov.b64 %0,{%1,%2};" : "=l"(r) : "f"(x), "f"(y)); return r;
}
__device__ __forceinline__ float2 unpack2(ull v) {
    float2 r; asm("mov.b64 {%0,%1},%2;" : "=f"(r.x), "=f"(r.y) : "l"(v)); return r;
}

// =====================================================================
// Kernel A: per-node GEMMs. 32 rows/block, thread = 2 rows x 8 cols.
// =====================================================================
#define ZSTR 260
__global__ __launch_bounds__(256, 2) void gat_prep(
    const float* __restrict__ node, const float* __restrict__ hidden,
    const float* __restrict__ m_w,  const float* __restrict__ m_b,
    const float* __restrict__ skip_w, const float* __restrict__ skip_b,
    const float* __restrict__ a1_w, const float* __restrict__ a1_b,
    const float* __restrict__ a2_w, const float* __restrict__ a2_b)
{
    extern __shared__ float sm[];
    float* zs = sm;              // 32 * ZSTR
    float* ws = sm + 32*ZSTR;    // 2 * 32*128 = 8192

    const int tid = threadIdx.x;
    const int r0  = blockIdx.x * 32;

    for (int t = tid; t < 32*64; t += 256) {
        int r = t >> 6, q = t & 63;
        float4 v = (q < 32) ? ((const float4*)node)[(r0 + r)*32 + q]
                            : ((const float4*)hidden)[(r0 + r)*32 + (q - 32)];
        *(float4*)&zs[r*ZSTR + q*4] = v;
    }

    const int cg = tid & 15;
    const int rg = tid >> 4;
    const int c0 = cg*4, c1 = 64 + cg*4;
    const int row0 = rg*2;

    ull av[2][4], ak[2][4];
    {
        ulonglong2 b0 = *(const ulonglong2*)&m_b[c0];
        ulonglong2 b1 = *(const ulonglong2*)&m_b[c1];
        ulonglong2 s0 = *(const ulonglong2*)&skip_b[c0];
        ulonglong2 s1 = *(const ulonglong2*)&skip_b[c1];
        #pragma unroll
        for (int rr = 0; rr < 2; ++rr) {
            av[rr][0]=b0.x; av[rr][1]=b0.y; av[rr][2]=b1.x; av[rr][3]=b1.y;
            ak[rr][0]=s0.x; ak[rr][1]=s0.y; ak[rr][2]=s1.x; ak[rr][3]=s1.y;
        }
    }

    for (int kk = 0; kk < 256; kk += 32) {
        __syncthreads();
        for (int t = tid; t < 2048; t += 256) {
            float4 v = (t < 1024) ? ((const float4*)m_w)[kk*32 + t]
                                  : ((const float4*)skip_w)[kk*32 + (t - 1024)];
            ((float4*)ws)[t] = v;
        }
        __syncthreads();
        #pragma unroll
        for (int k = 0; k < 32; ++k) {
            float z0 = zs[row0*ZSTR + kk + k];
            float z1 = zs[(row0+1)*ZSTR + kk + k];
            ulonglong2 wv0 = *(const ulonglong2*)&ws[k*128 + c0];
            ulonglong2 wv1 = *(const ulonglong2*)&ws[k*128 + c1];
            ulonglong2 wk0 = *(const ulonglong2*)&ws[4096 + k*128 + c0];
            ulonglong2 wk1 = *(const ulonglong2*)&ws[4096 + k*128 + c1];
            ull zz0 = pack2(z0, z0), zz1 = pack2(z1, z1);
            av[0][0]=ffma2(zz0,wv0.x,av[0][0]); av[0][1]=ffma2(zz0,wv0.y,av[0][1]);
            av[0][2]=ffma2(zz0,wv1.x,av[0][2]); av[0][3]=ffma2(zz0,wv1.y,av[0][3]);
            av[1][0]=ffma2(zz1,wv0.x,av[1][0]); av[1][1]=ffma2(zz1,wv0.y,av[1][1]);
            av[1][2]=ffma2(zz1,wv1.x,av[1][2]); av[1][3]=ffma2(zz1,wv1.y,av[1][3]);
            ak[0][0]=ffma2(zz0,wk0.x,ak[0][0]); ak[0][1]=ffma2(zz0,wk0.y,ak[0][1]);
            ak[0][2]=ffma2(zz0,wk1.x,ak[0][2]); ak[0][3]=ffma2(zz0,wk1.y,ak[0][3]);
            ak[1][0]=ffma2(zz1,wk0.x,ak[1][0]); ak[1][1]=ffma2(zz1,wk0.y,ak[1][1]);
            ak[1][2]=ffma2(zz1,wk1.x,ak[1][2]); ak[1][3]=ffma2(zz1,wk1.y,ak[1][3]);
        }
    }
    #pragma unroll
    for (int rr = 0; rr < 2; ++rr) {
        int rowg = r0 + row0 + rr;
        ulonglong2 o;
        o.x=av[rr][0]; o.y=av[rr][1]; *(ulonglong2*)&g_V[rowg*128 + c0] = o;
        o.x=av[rr][2]; o.y=av[rr][3]; *(ulonglong2*)&g_V[rowg*128 + c1] = o;
        o.x=ak[rr][0]; o.y=ak[rr][1]; *(ulonglong2*)&g_SKIP[rowg*128 + c0] = o;
        o.x=ak[rr][2]; o.y=ak[rr][3]; *(ulonglong2*)&g_SKIP[rowg*128 + c1] = o;
    }

    // ---- att1 / att2 tail ----
    __syncthreads();
    for (int t = tid; t < 2048; t += 256) {
        ws[t] = a1_w[t];
        ws[4096 + t] = a2_w[t];
    }
    __syncthreads();
    {
        int row = tid >> 3, h = tid & 7;
        float acc1 = a1_b[h], acc2 = a2_b[h];
        const float* zp = &zs[row*ZSTR];
        #pragma unroll 8
        for (int k = 0; k < 256; ++k) {
            float z = zp[k];
            acc1 = fmaf(z, ws[k*8 + h], acc1);
            acc2 = fmaf(z, ws[4096 + k*8 + h], acc2);
        }
        g_A1[(r0 + row)*8 + h] = acc1;
        g_A2[(r0 + row)*8 + h] = acc2;
    }
}

// =====================================================================
// Kernel B: att_g
// =====================================================================
__global__ void gat_attg(const float* __restrict__ graph,
                         const float* __restrict__ ag_w,
                         const float* __restrict__ ag_b)
{
    int t = threadIdx.x;
    if (t < 32) {
        int b = t >> 3, h = t & 7;
        float acc = ag_b[h];
        #pragma unroll 8
        for (int k = 0; k < 128; ++k)
            acc = fmaf(graph[b*128 + k], ag_w[k*8 + h], acc);
        g_ATTG[t] = acc;
    }
}

// =====================================================================
// Kernel C: fused attention. 256 thr, TI=16, TJ=32.
// Phase A: atte[i][h][j] once per (i,j) (edge read from gmem/L1).
// Phase B: f32x2 softmax over j-pairs + value accumulation.
// =====================================================================
#define ATTE_I 280   // per-i stride (>= 8*34), 280%32=24 -> bank-spread over il
__global__ __launch_bounds__(256, 2) void gat_attn(
    const float* __restrict__ edge, const int* __restrict__ adj,
    const float* __restrict__ ae_w, const float* __restrict__ ae_b,
    float* __restrict__ out)
{
    __shared__ float atte_s[TI*ATTE_I];   // 17.9KB
    __shared__ float vals_s[NH*516];      // 16.5KB
    __shared__ float adjf_s[TI*34];       // 2.2KB
    __shared__ float att2T_s[NH*36];      // 1.2KB
    __shared__ float red_s[128*17];       // 8.7KB

    const int tid = threadIdx.x;
    const int b   = blockIdx.x >> 6;      // 64 blocks per batch
    const int it  = blockIdx.x & 63;
    const int i0  = it * TI;

    // phase-A ids: group g handles heads 2g, 2g+1
    const int g  = tid >> 6;
    const int sA = tid & 63;
    // phase-B ids
    const int h  = tid & 7;
    const int il = (tid >> 3) & 15;
    const int hf = tid >> 7;

    // phase-A weights (d-pair packed) in regs
    ull aw0[8], aw1[8];
    #pragma unroll
    for (int q = 0; q < 8; ++q) {
        aw0[q] = pack2(ae_w[(2*q)*8 + 2*g],     ae_w[(2*q+1)*8 + 2*g]);
        aw1[q] = pack2(ae_w[(2*q)*8 + 2*g + 1], ae_w[(2*q+1)*8 + 2*g + 1]);
    }

    const float base = g_A1[(b*NN + i0 + il)*8 + h] + g_ATTG[b*8 + h] + ae_b[h];
    const ull base2 = pack2(base, base);

    const float CAf = 0.505f * 1.4426950408889634f;
    const float CBf = 0.495f * 1.4426950408889634f;
    const ull CA2    = pack2(CAf, CAf);
    const ull CB2    = pack2(CBf, CBf);
    const ull MAGIC2 = pack2(12582912.0f, 12582912.0f);
    const ull NMAG2  = pack2(-12582912.0f, -12582912.0f);
    const ull MONE2  = pack2(-1.0f, -1.0f);
    const ull P4     = pack2(0.0096181291f, 0.0096181291f);
    const ull P3     = pack2(0.0555041087f, 0.0555041087f);
    const ull P2     = pack2(0.2402265070f, 0.2402265070f);
    const ull P1     = pack2(0.6931471806f, 0.6931471806f);
    const ull ONE2   = pack2(1.0f, 1.0f);

    ull acc[8];
    #pragma unroll
    for (int q = 0; q < 8; ++q) acc[q] = 0ull;
    ull s2 = 0ull;

    for (int j0g = 0; j0g < NN; j0g += TJ) {
        __syncthreads();
        // stage values (L2-resident), swizzled to per-head rows
        for (int t = tid; t < TJ*32; t += 256) {
            int j = t >> 5, c4 = t & 31;
            float4 v = *(const float4*)&g_V[(b*NN + j0g + j)*128 + c4*4];
            int hh = c4 >> 2, d4 = c4 & 3;
            *(float4*)&vals_s[hh*516 + j*16 + d4*4] = v;
        }
        // adj as float mask
        for (int t = tid; t < TI*TJ; t += 256) {
            int i = t >> 5, j = t & 31;
            adjf_s[i*34 + j] = (float)adj[(b*NN + i0 + i)*NN + j0g + j];
        }
        // att2 transposed
        {
            int j = tid >> 3, hh = tid & 7;
            att2T_s[hh*36 + j] = g_A2[(b*NN + j0g + j)*8 + hh];
        }
        // phase A: att_e to smem (each (i,j) computed by 4 groups, 2 heads each)
        #pragma unroll 4
        for (int r = 0; r < 8; ++r) {
            int idx = r*64 + sA;
            int i = idx >> 5, j = idx & 31;
            const ulonglong2* ep =
                (const ulonglong2*)&edge[(size_t)((b*NN + i0 + i)*NN + j0g + j) * 16];
            ulonglong2 ea = ep[0], eb = ep[1], ec = ep[2], ed = ep[3];
            ull a0 = ffma2(ea.x, aw0[0], 0ull);
            ull a1 = ffma2(ea.x, aw1[0], 0ull);
            a0 = ffma2(ea.y, aw0[1], a0);  a1 = ffma2(ea.y, aw1[1], a1);
            a0 = ffma2(eb.x, aw0[2], a0);  a1 = ffma2(eb.x, aw1[2], a1);
            a0 = ffma2(eb.y, aw0[3], a0);  a1 = ffma2(eb.y, aw1[3], a1);
            a0 = ffma2(ec.x, aw0[4], a0);  a1 = ffma2(ec.x, aw1[4], a1);
            a0 = ffma2(ec.y, aw0[5], a0);  a1 = ffma2(ec.y, aw1[5], a1);
            a0 = ffma2(ed.x, aw0[6], a0);  a1 = ffma2(ed.x, aw1[6], a1);
            a0 = ffma2(ed.y, aw0[7], a0);  a1 = ffma2(ed.y, aw1[7], a1);
            float2 f0 = unpack2(a0), f1 = unpack2(a1);
            atte_s[i*ATTE_I + (2*g)*34 + j]     = f0.x + f0.y;
            atte_s[i*ATTE_I + (2*g + 1)*34 + j] = f1.x + f1.y;
        }
        __syncthreads();

        // phase B
        const float* ap  = &atte_s[il*ATTE_I + h*34];
        const float* a2p = &att2T_s[h*36];
        const float* adp = &adjf_s[il*34];
        const float* vp  = &vals_s[h*516];
        #pragma unroll
        for (int q = 0; q < 8; ++q) {
            int j0 = (hf*8 + q)*2;
            ull x2 = *(const ull*)&ap[j0];
            x2 = fadd2(x2, *(const ull*)&a2p[j0]);
            x2 = fadd2(x2, base2);
            ull ax = x2 & 0x7fffffff7fffffffULL;        // |x| per lane
            ull tt = fmul2(x2, CA2);
            tt = ffma2(ax, CB2, tt);                    // leaky*log2e
            ull r2 = fadd2(tt, MAGIC2);
            ull rm = fadd2(r2, NMAG2);
            ull f2 = ffma2(rm, MONE2, tt);              // frac part
            unsigned rl = (unsigned)r2, rh = (unsigned)(r2 >> 32);
            float sl = __int_as_float((int)((rl - 0x4B3FFF81u) << 23));
            float sh = __int_as_float((int)((rh - 0x4B3FFF81u) << 23));
            ull p2 = ffma2(P4, f2, P3);
            p2 = ffma2(p2, f2, P2);
            p2 = ffma2(p2, f2, P1);
            p2 = ffma2(p2, f2, ONE2);
            p2 = fmul2(p2, pack2(sl, sh));              // exp2
            p2 = fmul2(p2, *(const ull*)&adp[j0]);      // mask
            s2 = fadd2(s2, p2);
            float2 pf = unpack2(p2);
            ull pp0 = pack2(pf.x, pf.x);
            ull pp1 = pack2(pf.y, pf.y);
            const ulonglong2* v0 = (const ulonglong2*)&vp[j0*16];
            ulonglong2 va = v0[0], vb = v0[1], vc = v0[2], vd = v0[3];
            acc[0]=ffma2(pp0,va.x,acc[0]); acc[1]=ffma2(pp0,va.y,acc[1]);
            acc[2]=ffma2(pp0,vb.x,acc[2]); acc[3]=ffma2(pp0,vb.y,acc[3]);
            acc[4]=ffma2(pp0,vc.x,acc[4]); acc[5]=ffma2(pp0,vc.y,acc[5]);
            acc[6]=ffma2(pp0,vd.x,acc[6]); acc[7]=ffma2(pp0,vd.y,acc[7]);
            const ulonglong2* v1 = (const ulonglong2*)&vp[(j0 + 1)*16];
            va = v1[0]; vb = v1[1]; vc = v1[2]; vd = v1[3];
            acc[0]=ffma2(pp1,va.x,acc[0]); acc[1]=ffma2(pp1,va.y,acc[1]);
            acc[2]=ffma2(pp1,vb.x,acc[2]); acc[3]=ffma2(pp1,vb.y,acc[3]);
            acc[4]=ffma2(pp1,vc.x,acc[4]); acc[5]=ffma2(pp1,vc.y,acc[5]);
            acc[6]=ffma2(pp1,vd.x,acc[6]); acc[7]=ffma2(pp1,vd.y,acc[7]);
        }
    }

    // combine the two j-halves (fixed-shift softmax => plain adds)
    float accf[16];
    #pragma unroll
    for (int q = 0; q < 8; ++q) {
        float2 fv = unpack2(acc[q]);
        accf[2*q] = fv.x; accf[2*q+1] = fv.y;
    }
    float2 sf = unpack2(s2);
    float s = sf.x + sf.y;
    const int pr = il*8 + h;
    __syncthreads();
    if (hf) {
        #pragma unroll
        for (int d = 0; d < 16; ++d) red_s[pr*17 + d] = accf[d];
        red_s[pr*17 + 16] = s;
    }
    __syncthreads();
    if (!hf) {
        #pragma unroll
        for (int d = 0; d < 16; ++d) accf[d] += red_s[pr*17 + d];
        s += red_s[pr*17 + 16];
        float inv = 1.0f / s;
        int ob = (b*NN + i0 + il)*128 + h*16;
        #pragma unroll
        for (int q = 0; q < 4; ++q) {
            float4 sk = *(const float4*)&g_SKIP[ob + q*4];
            float4 o;
            o.x = fmaxf(fmaf(accf[q*4+0], inv, sk.x), 0.0f);
            o.y = fmaxf(fmaf(accf[q*4+1], inv, sk.y), 0.0f);
            o.z = fmaxf(fmaf(accf[q*4+2], inv, sk.z), 0.0f);
            o.w = fmaxf(fmaf(accf[q*4+3], inv, sk.w), 0.0f);
            *(float4*)&out[ob + q*4] = o;
        }
    }
}

// =====================================================================
extern "C" void kernel_launch(void* const* d_in, const int* in_sizes, int n_in,
                              void* d_out, int out_size)
{
    const float* node   = (const float*)d_in[0];
    const float* edge   = (const float*)d_in[1];
    const float* graph  = (const float*)d_in[2];
    const int*   adj    = (const int*)  d_in[3];
    const float* hidden = (const float*)d_in[4];
    const float* m_w    = (const float*)d_in[5];
    const float* m_b    = (const float*)d_in[6];
    const float* skip_w = (const float*)d_in[7];
    const float* skip_b = (const float*)d_in[8];
    const float* a1_w   = (const float*)d_in[9];
    const float* a1_b   = (const float*)d_in[10];
    const float* a2_w   = (const float*)d_in[11];
    const float* a2_b   = (const float*)d_in[12];
    const float* ae_w   = (const float*)d_in[13];
    const float* ae_b   = (const float*)d_in[14];
    const float* ag_w   = (const float*)d_in[15];
    const float* ag_b   = (const float*)d_in[16];
    float* out = (float*)d_out;

    const int prep_smem = (32*ZSTR + 2*32*128) * 4;   // 66048 B
    cudaFuncSetAttribute(gat_prep, cudaFuncAttributeMaxDynamicSharedMemorySize,
                         prep_smem);

    gat_prep<<<BN/32, 256, prep_smem>>>(node, hidden, m_w, m_b, skip_w, skip_b,
                                        a1_w, a1_b, a2_w, a2_b);
    gat_attg<<<1, 32>>>(graph, ag_w, ag_b);
    gat_attn<<<4 * (NN/TI), 256>>>(edge, adj, ae_w, ae_b, out);
}

// round 3
// speedup vs baseline: 1.7165x; 1.7165x over previous
#include <cuda_runtime.h>

#define NN 1024
#define BN 4096
#define NH 8
#define TI 16
#define TJ 32

typedef unsigned long long ull;

// ---- scratch ----
__device__ float g_V[BN*128];
__device__ float g_SKIP[BN*128];
__device__ float g_A1[BN*NH];
__device__ float g_A2[BN*NH];
__device__ float g_ATTG[4*NH];

// ---- packed f32x2 helpers ----
__device__ __forceinline__ ull ffma2(ull a, ull b, ull c) {
    ull d; asm("fma.rn.f32x2 %0,%1,%2,%3;" : "=l"(d) : "l"(a), "l"(b), "l"(c)); return d;
}
__device__ __forceinline__ ull fadd2(ull a, ull b) {
    ull d; asm("add.rn.f32x2 %0,%1,%2;" : "=l"(d) : "l"(a), "l"(b)); return d;
}
__device__ __forceinline__ ull fmul2(ull a, ull b) {
    ull d; asm("mul.rn.f32x2 %0,%1,%2;" : "=l"(d) : "l"(a), "l"(b)); return d;
}
__device__ __forceinline__ ull pack2(float x, float y) {
    ull r; asm("mov.b64 %0,{%1,%2};" : "=l"(r) : "f"(x), "f"(y)); return r;
}
__device__ __forceinline__ float2 unpack2(ull v) {
    float2 r; asm("mov.b64 {%0,%1},%2;" : "=f"(r.x), "=f"(r.y) : "l"(v)); return r;
}
__device__ __forceinline__ ull shflx2(ull v, int m) {
    unsigned lo = (unsigned)v, hi = (unsigned)(v >> 32);
    lo = __shfl_xor_sync(0xffffffffu, lo, m);
    hi = __shfl_xor_sync(0xffffffffu, hi, m);
    return ((ull)hi << 32) | (ull)lo;
}

// =====================================================================
// Kernel A: per-node GEMMs. 32 rows/block, thread = 4 rows x 4 cols.
// Weights read from smem ONCE per 4 rows (crossbar traffic /2 vs R1).
// =====================================================================
#define ZSTR 260
__global__ __launch_bounds__(256) void gat_prep(
    const float* __restrict__ node, const float* __restrict__ hidden,
    const float* __restrict__ m_w,  const float* __restrict__ m_b,
    const float* __restrict__ skip_w, const float* __restrict__ skip_b,
    const float* __restrict__ a1_w, const float* __restrict__ a1_b,
    const float* __restrict__ a2_w, const float* __restrict__ a2_b)
{
    extern __shared__ float sm[];
    float* zs = sm;              // 32 * ZSTR
    float* ws = sm + 32*ZSTR;    // 8192 floats

    const int tid = threadIdx.x;
    const int r0  = blockIdx.x * 32;

    for (int t = tid; t < 32*64; t += 256) {
        int r = t >> 6, q = t & 63;
        float4 v = (q < 32) ? ((const float4*)node)[(r0 + r)*32 + q]
                            : ((const float4*)hidden)[(r0 + r)*32 + (q - 32)];
        *(float4*)&zs[r*ZSTR + q*4] = v;
    }

    const int cg = tid & 31;       // 32 col-groups of 4 cols
    const int rg = tid >> 5;       // 8 row-groups of 4 rows
    const int c0 = cg * 4;
    const int rowb = rg * 4;

    ull av[4][2], ak[4][2];
    {
        ulonglong2 bv = *(const ulonglong2*)&m_b[c0];
        ulonglong2 bk = *(const ulonglong2*)&skip_b[c0];
        #pragma unroll
        for (int rr = 0; rr < 4; ++rr) {
            av[rr][0] = bv.x; av[rr][1] = bv.y;
            ak[rr][0] = bk.x; ak[rr][1] = bk.y;
        }
    }

    for (int kk = 0; kk < 256; kk += 32) {
        __syncthreads();
        for (int t = tid; t < 2048; t += 256) {
            float4 v = (t < 1024) ? ((const float4*)m_w)[kk*32 + t]
                                  : ((const float4*)skip_w)[kk*32 + (t - 1024)];
            ((float4*)ws)[t] = v;
        }
        __syncthreads();
        #pragma unroll
        for (int k = 0; k < 32; ++k) {
            ulonglong2 wv = *(const ulonglong2*)&ws[k*128 + c0];
            ulonglong2 wk = *(const ulonglong2*)&ws[4096 + k*128 + c0];
            #pragma unroll
            for (int rr = 0; rr < 4; ++rr) {
                float z = zs[(rowb + rr)*ZSTR + kk + k];
                ull zz = pack2(z, z);
                av[rr][0] = ffma2(zz, wv.x, av[rr][0]);
                av[rr][1] = ffma2(zz, wv.y, av[rr][1]);
                ak[rr][0] = ffma2(zz, wk.x, ak[rr][0]);
                ak[rr][1] = ffma2(zz, wk.y, ak[rr][1]);
            }
        }
    }
    #pragma unroll
    for (int rr = 0; rr < 4; ++rr) {
        int rowg = r0 + rowb + rr;
        ulonglong2 o;
        o.x = av[rr][0]; o.y = av[rr][1];
        *(ulonglong2*)&g_V[rowg*128 + c0] = o;
        o.x = ak[rr][0]; o.y = ak[rr][1];
        *(ulonglong2*)&g_SKIP[rowg*128 + c0] = o;
    }

    // ---- att1 / att2 tail ----
    __syncthreads();
    for (int t = tid; t < 2048; t += 256) {
        ws[t] = a1_w[t];
        ws[4096 + t] = a2_w[t];
    }
    __syncthreads();
    {
        int row = tid >> 3, h = tid & 7;
        float acc1 = a1_b[h], acc2 = a2_b[h];
        const float* zp = &zs[row*ZSTR];
        #pragma unroll 8
        for (int k = 0; k < 256; ++k) {
            float z = zp[k];
            acc1 = fmaf(z, ws[k*8 + h], acc1);
            acc2 = fmaf(z, ws[4096 + k*8 + h], acc2);
        }
        g_A1[(r0 + row)*8 + h] = acc1;
        g_A2[(r0 + row)*8 + h] = acc2;
    }
}

// =====================================================================
// Kernel B: att_g
// =====================================================================
__global__ void gat_attg(const float* __restrict__ graph,
                         const float* __restrict__ ag_w,
                         const float* __restrict__ ag_b)
{
    int t = threadIdx.x;
    if (t < 32) {
        int b = t >> 3, h = t & 7;
        float acc = ag_b[h];
        #pragma unroll 8
        for (int k = 0; k < 128; ++k)
            acc = fmaf(graph[b*128 + k], ag_w[k*8 + h], acc);
        g_ATTG[t] = acc;
    }
}

// =====================================================================
// Kernel C: fused attention.
// Phase A: each thread owns one (i,j): 64B edge read ONCE from gmem,
//          all 8 heads via f32x2 head-pairs, weights broadcast from smem.
// Phase B: thread = (h, i-pair, j-quarter); softmax packed over i-pair;
//          value vector shared (broadcast) across the 8 i-pair lanes.
// =====================================================================
__global__ __launch_bounds__(256, 2) void gat_attn(
    const float* __restrict__ edge, const int* __restrict__ adj,
    const float* __restrict__ ae_w, const float* __restrict__ ae_b,
    float* __restrict__ out)
{
    __shared__ float atte2_s[NH*544];      // [h][ip][j(34)][io]  17.4KB
    __shared__ float vals_s[NH*640];       // [h][j*20 + d]       20.5KB
    __shared__ float adj2_s[8*68];         // [ip][j(34)][io]      2.2KB
    __shared__ float att2T_s[NH*36];       // [h][j]
    __shared__ ulonglong2 w2s2[32];        // [d][hp01 | hp23]

    const int tid  = threadIdx.x;
    const int b    = blockIdx.x >> 6;
    const int it   = blockIdx.x & 63;
    const int i0   = it * TI;
    const int h    = tid >> 5;
    const int lane = tid & 31;
    const int ip   = lane >> 2;
    const int jq   = lane & 3;

    if (tid < 64) ((ull*)w2s2)[tid] = ((const ull*)ae_w)[tid];

    ull base2;
    {
        float gh = g_ATTG[b*8 + h] + ae_b[h];
        float b0 = g_A1[(b*NN + i0 + 2*ip)*8 + h] + gh;
        float b1 = g_A1[(b*NN + i0 + 2*ip + 1)*8 + h] + gh;
        base2 = pack2(b0, b1);
    }

    const float CAf = 0.505f * 1.4426950408889634f;
    const float CBf = 0.495f * 1.4426950408889634f;
    const ull CA2    = pack2(CAf, CAf);
    const ull CB2    = pack2(CBf, CBf);
    const ull MAGIC2 = pack2(12582912.0f, 12582912.0f);
    const ull NMAG2  = pack2(-12582912.0f, -12582912.0f);
    const ull MONE2  = pack2(-1.0f, -1.0f);
    const ull P4     = pack2(0.0096181291f, 0.0096181291f);
    const ull P3     = pack2(0.0555041087f, 0.0555041087f);
    const ull P2     = pack2(0.2402265070f, 0.2402265070f);
    const ull P1     = pack2(0.6931471806f, 0.6931471806f);
    const ull ONE2   = pack2(1.0f, 1.0f);

    ull acc0[8], acc1[8];
    #pragma unroll
    for (int q = 0; q < 8; ++q) { acc0[q] = 0ull; acc1[q] = 0ull; }
    ull s2 = 0ull;

    for (int j0g = 0; j0g < NN; j0g += TJ) {
        __syncthreads();
        // stage values: [h][j*20+d], 64B gmem chunks
        for (int t = tid; t < 1024; t += 256) {
            int d4 = t & 3, j = (t >> 2) & 31, hh = t >> 7;
            float4 v = *(const float4*)&g_V[(b*NN + j0g + j)*128 + hh*16 + d4*4];
            *(float4*)&vals_s[hh*640 + j*20 + d4*4] = v;
        }
        // adj, i-pair interleaved
        {
            int ipg = tid >> 5, j = tid & 31;
            float a0 = (float)adj[(b*NN + i0 + 2*ipg)*NN + j0g + j];
            float a1 = (float)adj[(b*NN + i0 + 2*ipg + 1)*NN + j0g + j];
            float2 av; av.x = a0; av.y = a1;
            *(float2*)&adj2_s[(ipg*34 + j)*2] = av;
        }
        // att2 transposed
        {
            int j = tid >> 3, hh = tid & 7;
            att2T_s[hh*36 + j] = g_A2[(b*NN + j0g + j)*8 + hh];
        }
        // phase A: one thread per (i,j), edge read once
        #pragma unroll
        for (int pp = 0; pp < 2; ++pp) {
            int p = pp*256 + tid;
            int i = p >> 5, j = p & 31;
            const float4* ep =
                (const float4*)&edge[(size_t)((b*NN + i0 + i)*NN + j0g + j) * 16];
            float4 e0 = __ldcs(ep + 0);
            float4 e1 = __ldcs(ep + 1);
            float4 e2 = __ldcs(ep + 2);
            float4 e3 = __ldcs(ep + 3);
            ull a0 = 0ull, a1 = 0ull, a2 = 0ull, a3 = 0ull;
            #define PA_STEP(dd, ev) { \
                ull ee = pack2(ev, ev); \
                ulonglong2 wA = w2s2[(dd)*2]; \
                ulonglong2 wB = w2s2[(dd)*2 + 1]; \
                a0 = ffma2(ee, wA.x, a0); a1 = ffma2(ee, wA.y, a1); \
                a2 = ffma2(ee, wB.x, a2); a3 = ffma2(ee, wB.y, a3); }
            PA_STEP(0,  e0.x) PA_STEP(1,  e0.y) PA_STEP(2,  e0.z) PA_STEP(3,  e0.w)
            PA_STEP(4,  e1.x) PA_STEP(5,  e1.y) PA_STEP(6,  e1.z) PA_STEP(7,  e1.w)
            PA_STEP(8,  e2.x) PA_STEP(9,  e2.y) PA_STEP(10, e2.z) PA_STEP(11, e2.w)
            PA_STEP(12, e3.x) PA_STEP(13, e3.y) PA_STEP(14, e3.z) PA_STEP(15, e3.w)
            #undef PA_STEP
            int bidx = ((i >> 1)*34 + j)*2 + (i & 1);
            float2 f0 = unpack2(a0), f1 = unpack2(a1);
            float2 f2 = unpack2(a2), f3 = unpack2(a3);
            atte2_s[0*544 + bidx] = f0.x;
            atte2_s[1*544 + bidx] = f0.y;
            atte2_s[2*544 + bidx] = f1.x;
            atte2_s[3*544 + bidx] = f1.y;
            atte2_s[4*544 + bidx] = f2.x;
            atte2_s[5*544 + bidx] = f2.y;
            atte2_s[6*544 + bidx] = f3.x;
            atte2_s[7*544 + bidx] = f3.y;
        }
        __syncthreads();

        // phase B
        const float* ap  = &atte2_s[h*544 + ip*68];
        const float* vp  = &vals_s[h*640];
        const float* a2p = &att2T_s[h*36];
        const float* adp = &adj2_s[ip*68];
        #pragma unroll
        for (int jj = 0; jj < 8; ++jj) {
            int j = jj*4 + jq;
            ull x2 = *(const ull*)&ap[j*2];
            float a2v = a2p[j];
            x2 = fadd2(x2, base2);
            x2 = fadd2(x2, pack2(a2v, a2v));
            ull ax = x2 & 0x7fffffff7fffffffULL;
            ull tt = fmul2(x2, CA2);
            tt = ffma2(ax, CB2, tt);
            ull r2 = fadd2(tt, MAGIC2);
            ull rm = fadd2(r2, NMAG2);
            ull f2 = ffma2(rm, MONE2, tt);
            unsigned rl = (unsigned)r2, rh = (unsigned)(r2 >> 32);
            float sl = __int_as_float((int)((rl - 0x4B3FFF81u) << 23));
            float sh = __int_as_float((int)((rh - 0x4B3FFF81u) << 23));
            ull p2 = ffma2(P4, f2, P3);
            p2 = ffma2(p2, f2, P2);
            p2 = ffma2(p2, f2, P1);
            p2 = ffma2(p2, f2, ONE2);
            p2 = fmul2(p2, pack2(sl, sh));
            p2 = fmul2(p2, *(const ull*)&adp[j*2]);
            s2 = fadd2(s2, p2);
            float2 pf = unpack2(p2);
            ull pp0 = pack2(pf.x, pf.x);
            ull pp1 = pack2(pf.y, pf.y);
            ulonglong2 va = *(const ulonglong2*)&vp[j*20];
            ulonglong2 vb = *(const ulonglong2*)&vp[j*20 + 4];
            ulonglong2 vc = *(const ulonglong2*)&vp[j*20 + 8];
            ulonglong2 vd = *(const ulonglong2*)&vp[j*20 + 12];
            acc0[0]=ffma2(pp0,va.x,acc0[0]); acc0[1]=ffma2(pp0,va.y,acc0[1]);
            acc0[2]=ffma2(pp0,vb.x,acc0[2]); acc0[3]=ffma2(pp0,vb.y,acc0[3]);
            acc0[4]=ffma2(pp0,vc.x,acc0[4]); acc0[5]=ffma2(pp0,vc.y,acc0[5]);
            acc0[6]=ffma2(pp0,vd.x,acc0[6]); acc0[7]=ffma2(pp0,vd.y,acc0[7]);
            acc1[0]=ffma2(pp1,va.x,acc1[0]); acc1[1]=ffma2(pp1,va.y,acc1[1]);
            acc1[2]=ffma2(pp1,vb.x,acc1[2]); acc1[3]=ffma2(pp1,vb.y,acc1[3]);
            acc1[4]=ffma2(pp1,vc.x,acc1[4]); acc1[5]=ffma2(pp1,vc.y,acc1[5]);
            acc1[6]=ffma2(pp1,vd.x,acc1[6]); acc1[7]=ffma2(pp1,vd.y,acc1[7]);
        }
    }

    // reduce across j-quarters (lane bits 0-1)
    #pragma unroll
    for (int m = 1; m <= 2; m <<= 1) {
        #pragma unroll
        for (int q = 0; q < 8; ++q) {
            acc0[q] = fadd2(acc0[q], shflx2(acc0[q], m));
            acc1[q] = fadd2(acc1[q], shflx2(acc1[q], m));
        }
        s2 = fadd2(s2, shflx2(s2, m));
    }
    if (jq == 0) {
        float2 sf = unpack2(s2);
        float inv0 = 1.0f / sf.x;
        float inv1 = 1.0f / sf.y;
        int r0o = (b*NN + i0 + 2*ip)*128 + h*16;
        #pragma unroll
        for (int q4 = 0; q4 < 4; ++q4) {
            float4 sk = *(const float4*)&g_SKIP[r0o + q4*4];
            float2 u0 = unpack2(acc0[q4*2]), u1 = unpack2(acc0[q4*2 + 1]);
            float4 o;
            o.x = fmaxf(fmaf(u0.x, inv0, sk.x), 0.0f);
            o.y = fmaxf(fmaf(u0.y, inv0, sk.y), 0.0f);
            o.z = fmaxf(fmaf(u1.x, inv0, sk.z), 0.0f);
            o.w = fmaxf(fmaf(u1.y, inv0, sk.w), 0.0f);
            *(float4*)&out[r0o + q4*4] = o;
        }
        int r1o = r0o + 128;
        #pragma unroll
        for (int q4 = 0; q4 < 4; ++q4) {
            float4 sk = *(const float4*)&g_SKIP[r1o + q4*4];
            float2 u0 = unpack2(acc1[q4*2]), u1 = unpack2(acc1[q4*2 + 1]);
            float4 o;
            o.x = fmaxf(fmaf(u0.x, inv1, sk.x), 0.0f);
            o.y = fmaxf(fmaf(u0.y, inv1, sk.y), 0.0f);
            o.z = fmaxf(fmaf(u1.x, inv1, sk.z), 0.0f);
            o.w = fmaxf(fmaf(u1.y, inv1, sk.w), 0.0f);
            *(float4*)&out[r1o + q4*4] = o;
        }
    }
}

// =====================================================================
extern "C" void kernel_launch(void* const* d_in, const int* in_sizes, int n_in,
                              void* d_out, int out_size)
{
    const float* node   = (const float*)d_in[0];
    const float* edge   = (const float*)d_in[1];
    const float* graph  = (const float*)d_in[2];
    const int*   adj    = (const int*)  d_in[3];
    const float* hidden = (const float*)d_in[4];
    const float* m_w    = (const float*)d_in[5];
    const float* m_b    = (const float*)d_in[6];
    const float* skip_w = (const float*)d_in[7];
    const float* skip_b = (const float*)d_in[8];
    const float* a1_w   = (const float*)d_in[9];
    const float* a1_b   = (const float*)d_in[10];
    const float* a2_w   = (const float*)d_in[11];
    const float* a2_b   = (const float*)d_in[12];
    const float* ae_w   = (const float*)d_in[13];
    const float* ae_b   = (const float*)d_in[14];
    const float* ag_w   = (const float*)d_in[15];
    const float* ag_b   = (const float*)d_in[16];
    float* out = (float*)d_out;

    const int prep_smem = (32*ZSTR + 8192) * 4;
    cudaFuncSetAttribute(gat_prep, cudaFuncAttributeMaxDynamicSharedMemorySize,
                         prep_smem);

    gat_prep<<<BN/32, 256, prep_smem>>>(node, hidden, m_w, m_b, skip_w, skip_b,
                                        a1_w, a1_b, a2_w, a2_b);
    gat_attg<<<1, 32>>>(graph, ag_w, ag_b);
    gat_attn<<<4 * (NN/TI), 256>>>(edge, adj, ae_w, ae_b, out);
}